// round 15
// baseline (speedup 1.0000x reference)
#include <cuda_runtime.h>
#include <cuda_fp16.h>
#include <math.h>
#include <stdint.h>

// Problem shape (fixed): B=16384 rows, D=1024, grid 32x32 -> N=1024 codes
#define BROWS 16384
#define DIM   1024
#define NCODE 1024

// ---------------- scratch (__device__ globals; allocation-free rule) -------
__device__ float g_logits[(size_t)BROWS * NCODE];    // 64MB
__device__ float g_wsq[NCODE];
__device__ __half g_xhi[(size_t)BROWS * DIM];
__device__ __half g_xlo[(size_t)BROWS * DIM];
__device__ __half g_whi[(size_t)NCODE * DIM];
__device__ __half g_wthi[(size_t)DIM * NCODE];
__device__ __half g_phi[(size_t)BROWS * NCODE];

// ---------------- PTX helpers ----------------------------------------------
__device__ __forceinline__ uint32_t s2u(const void* p) {
    uint32_t a;
    asm("{ .reg .u64 t; cvta.to.shared.u64 t, %1; cvt.u32.u64 %0, t; }" : "=r"(a) : "l"(p));
    return a;
}
__device__ __forceinline__ uint32_t swz128(uint32_t o) { return o ^ ((o >> 3) & 0x70); }

__device__ __forceinline__ void cpa16(uint32_t dst, const void* src) {
    asm volatile("cp.async.cg.shared.global [%0], [%1], 16;" :: "r"(dst), "l"(src));
}
#define CP_COMMIT() asm volatile("cp.async.commit_group;")
#define CP_WAIT(n)  asm volatile("cp.async.wait_group %0;" :: "n"(n))

__device__ __forceinline__ void ldsm_x4(uint32_t* r, uint32_t addr) {
    asm volatile("ldmatrix.sync.aligned.m8n8.x4.shared.b16 {%0,%1,%2,%3}, [%4];"
                 : "=r"(r[0]), "=r"(r[1]), "=r"(r[2]), "=r"(r[3]) : "r"(addr));
}
__device__ __forceinline__ void mma16816(float* d, const uint32_t* a, const uint32_t* b) {
    asm volatile("mma.sync.aligned.m16n8k16.row.col.f32.f16.f16.f32 "
                 "{%0,%1,%2,%3}, {%4,%5,%6,%7}, {%8,%9}, {%0,%1,%2,%3};"
                 : "+f"(d[0]), "+f"(d[1]), "+f"(d[2]), "+f"(d[3])
                 : "r"(a[0]), "r"(a[1]), "r"(a[2]), "r"(a[3]), "r"(b[0]), "r"(b[1]));
}
// f16-accumulator HMMA (for small correction term)
__device__ __forceinline__ void mma16816h(uint32_t* d, const uint32_t* a, const uint32_t* b) {
    asm volatile("mma.sync.aligned.m16n8k16.row.col.f16.f16.f16.f16 "
                 "{%0,%1}, {%2,%3,%4,%5}, {%6,%7}, {%0,%1};"
                 : "+r"(d[0]), "+r"(d[1])
                 : "r"(a[0]), "r"(a[1]), "r"(a[2]), "r"(a[3]), "r"(b[0]), "r"(b[1]));
}

// ---------------- small kernels ---------------------------------------------
__global__ void wsq_kernel(const float* __restrict__ W, float* __restrict__ wsq) {
    const int n = blockIdx.x, tid = threadIdx.x;
    const float4 v = *reinterpret_cast<const float4*>(W + (size_t)n * DIM + tid * 4);
    float s = v.x * v.x + v.y * v.y + v.z * v.z + v.w * v.w;
    __shared__ float red[256];
    red[tid] = s;
    __syncthreads();
    #pragma unroll
    for (int st = 128; st > 0; st >>= 1) {
        if (tid < st) red[tid] += red[tid + st];
        __syncthreads();
    }
    if (tid == 0) wsq[n] = red[0];
}

// hi = f16(v), lo = f16(v - hi). 4 elems/thread. (x only)
__global__ void split_kernel(const float* __restrict__ src,
                             __half* __restrict__ hi, __half* __restrict__ lo, int n4) {
    int i = blockIdx.x * blockDim.x + threadIdx.x;
    if (i >= n4) return;
    float4 v = reinterpret_cast<const float4*>(src)[i];
    __half h0 = __float2half_rn(v.x), h1 = __float2half_rn(v.y);
    __half h2 = __float2half_rn(v.z), h3 = __float2half_rn(v.w);
    __half l0 = __float2half_rn(v.x - __half2float(h0));
    __half l1 = __float2half_rn(v.y - __half2float(h1));
    __half l2 = __float2half_rn(v.z - __half2float(h2));
    __half l3 = __float2half_rn(v.w - __half2float(h3));
    __half2* ph = reinterpret_cast<__half2*>(hi) + 2 * i;
    __half2* pl = reinterpret_cast<__half2*>(lo) + 2 * i;
    ph[0] = __halves2half2(h0, h1); ph[1] = __halves2half2(h2, h3);
    pl[0] = __halves2half2(l0, l1); pl[1] = __halves2half2(l2, l3);
}

// W prep (fused): whi[n][d] = f16(W[n][d]); wthi[d][n] = f16(W[n][d]).
__global__ void wprep_kernel(const float* __restrict__ W,
                             __half* __restrict__ Whi,
                             __half* __restrict__ WThi) {
    __shared__ float tile[32][33];
    const int tx = threadIdx.x, ty = threadIdx.y;
    const int bd = blockIdx.x, bn = blockIdx.y;
    const float v = W[(size_t)(bn * 32 + ty) * DIM + bd * 32 + tx];
    tile[ty][tx] = v;
    Whi[(size_t)(bn * 32 + ty) * DIM + bd * 32 + tx] = __float2half_rn(v);
    __syncthreads();
    WThi[(size_t)(bd * 32 + ty) * NCODE + bn * 32 + tx] = __float2half_rn(tile[tx][ty]);
}

// per-row double softmax + product + normalize; emits fp16 P.
__global__ void combine_kernel(const float* __restrict__ L,
                               __half* __restrict__ Phi) {
    const int b = blockIdx.x, tid = threadIdx.x;
    const int lane = tid & 31, wp = tid >> 5;
    const float* row = L + (size_t)b * 1024;

    __shared__ float sh_e[1024 + 32];  // stride-33 padded
    __shared__ float wred[8];
    __shared__ float iRS[32], iCS[32];
    __shared__ float sh_bcast[2];

    const int n0 = tid * 4;
    float4 v = *reinterpret_cast<const float4*>(row + n0);

    float m = fmaxf(fmaxf(v.x, v.y), fmaxf(v.z, v.w));
    #pragma unroll
    for (int s = 16; s > 0; s >>= 1)
        m = fmaxf(m, __shfl_xor_sync(0xffffffffu, m, s));
    if (lane == 0) wred[wp] = m;
    __syncthreads();
    if (tid == 0) {
        float mm = wred[0];
        #pragma unroll
        for (int i = 1; i < 8; i++) mm = fmaxf(mm, wred[i]);
        sh_bcast[0] = mm;
    }
    __syncthreads();
    const float M = sh_bcast[0];

    const float e0 = __expf(v.x - M), e1 = __expf(v.y - M);
    const float e2 = __expf(v.z - M), e3 = __expf(v.w - M);
    sh_e[(n0 + 0) + ((n0 + 0) >> 5)] = e0;
    sh_e[(n0 + 1) + ((n0 + 1) >> 5)] = e1;
    sh_e[(n0 + 2) + ((n0 + 2) >> 5)] = e2;
    sh_e[(n0 + 3) + ((n0 + 3) >> 5)] = e3;
    __syncthreads();

    if (tid < 32) {
        float s = 0.f;
        #pragma unroll
        for (int j = 0; j < 32; j++) s += sh_e[tid * 33 + j];
        iRS[tid] = __fdividef(1.f, s);
    } else if (tid < 64) {
        const int g2 = tid - 32;
        float s = 0.f;
        #pragma unroll
        for (int j = 0; j < 32; j++) s += sh_e[j * 33 + g2];
        iCS[g2] = __fdividef(1.f, s);
    }
    __syncthreads();

    const int g1 = n0 >> 5, g2 = n0 & 31;
    const float irs = iRS[g1];
    const float c0 = e0 * e0 * irs * iCS[g2 + 0];
    const float c1 = e1 * e1 * irs * iCS[g2 + 1];
    const float c2 = e2 * e2 * irs * iCS[g2 + 2];
    const float c3 = e3 * e3 * irs * iCS[g2 + 3];

    float s = c0 + c1 + c2 + c3;
    #pragma unroll
    for (int st = 16; st > 0; st >>= 1)
        s += __shfl_xor_sync(0xffffffffu, s, st);
    if (lane == 0) wred[wp] = s;
    __syncthreads();
    if (tid == 0) {
        float ss = 0.f;
        #pragma unroll
        for (int i = 0; i < 8; i++) ss += wred[i];
        sh_bcast[1] = __fdividef(1.0f, ss + 1e-8f);
    }
    __syncthreads();
    const float inv = sh_bcast[1];

    __half h0 = __float2half_rn(c0 * inv), h1 = __float2half_rn(c1 * inv);
    __half h2 = __float2half_rn(c2 * inv), h3 = __float2half_rn(c3 * inv);
    __half2* ph = reinterpret_cast<__half2*>(Phi + (size_t)b * 1024 + n0);
    ph[0] = __halves2half2(h0, h1); ph[1] = __halves2half2(h2, h3);
}

// ---------------- mma.sync split-fp16 GEMM -----------------------------------
// CTA 128(m)x64(n), 256 threads = 8 warps (4m x 2n), warp tile 32x32.
// TWO CTAs per SM (independent barriers -> tensor pipe stays fed across
// stage-boundary drains). K-stage 64 (128B SW128 rows).
// TERMS==2: 2-stage pipeline (smem 2x40KB/CTA); TERMS==1: 3-stage (3x24KB),
//           distance-2 loads into the OLDEST slot (R14 bug: distance-3 wrote
//           the live slot).
// Register fragment pipeline across k16 as in R13.
// EPI==1: C = 2*acc - wsq[col].
#define TILE_A16  16384                // 128 rows x 128B
#define TILE_B16  8192                 //  64 rows x 128B
#define TSTAGES   16                   // 1024 / 64

template<int EPI, int TERMS>
__global__ __launch_bounds__(256, 2)
void mma_gemm(const __half* __restrict__ Ahi, const __half* __restrict__ Alo,
              const __half* __restrict__ Bhi,
              float* __restrict__ C, const float* __restrict__ wsq)
{
    constexpr bool HAS_CORR = (TERMS == 2);
    constexpr int  NSTAGES  = HAS_CORR ? 2 : 3;
    constexpr uint32_t OFF_ALO = TILE_A16;
    constexpr uint32_t OFF_BHI = HAS_CORR ? 2 * TILE_A16 : TILE_A16;
    constexpr uint32_t STAGE_B = OFF_BHI + TILE_B16;

    extern __shared__ char dyn[];
    const uint32_t sbase = (s2u(dyn) + 1023u) & ~1023u;

    const int tid  = threadIdx.x;
    const int w    = tid >> 5, lane = tid & 31;
    const int nT   = blockIdx.x, mT = blockIdx.y;
    const int wm   = (w >> 1) * 32;    // 4 warps along m
    const int wn   = (w & 1) * 32;     // 2 warps along n

    // ---- gmem loader geometry ------------------------------------------------
    // A: 128 rows, 2 threads/row, each 4x16B.  B: 64 rows, 4 threads/row, 2x16B.
    const int ar = tid >> 1;
    const uint32_t ac = (tid & 1) * 64;
    const int br = tid >> 2;
    const uint32_t bc = (tid & 3) * 32;
    uint32_t aso[4], bso[2];
    #pragma unroll
    for (int i = 0; i < 4; i++) aso[i] = swz128((uint32_t)ar * 128u + ac + i * 16);
    #pragma unroll
    for (int i = 0; i < 2; i++) bso[i] = swz128((uint32_t)br * 128u + bc + i * 16);

    const char* gAhi = (const char*)Ahi + (size_t)(mT * 128 + ar) * 2048 + ac;
    const char* gAlo = HAS_CORR ? (const char*)Alo + (size_t)(mT * 128 + ar) * 2048 + ac : nullptr;
    const char* gBhi = (const char*)Bhi + (size_t)(nT * 64 + br) * 2048 + bc;

    auto load_stage = [&](int t, int slot) {
        const uint32_t sb = sbase + (uint32_t)slot * STAGE_B;
        const size_t tb = (size_t)t * 128;   // 64 f16 = 128B along K
        #pragma unroll
        for (int i = 0; i < 4; i++) {
            cpa16(sb + aso[i], gAhi + tb + i * 16);
            if (HAS_CORR) cpa16(sb + OFF_ALO + aso[i], gAlo + tb + i * 16);
        }
        #pragma unroll
        for (int i = 0; i < 2; i++)
            cpa16(sb + OFF_BHI + bso[i], gBhi + tb + i * 16);
        CP_COMMIT();
    };

    // ---- ldmatrix base addresses (swizzled; k-step folds in via XOR) -------
    uint32_t a0[2];
    {
        const int rsel = (lane >> 4) * 16;
        #pragma unroll
        for (int mi = 0; mi < 2; mi++) {
            const int row = wm + mi * 16 + (lane & 15);
            a0[mi] = (uint32_t)row * 128u + (uint32_t)(rsel ^ ((row & 7) << 4));
        }
    }
    uint32_t b0[2];
    {
        const int selb = ((lane >> 3) & 1) * 16;
        #pragma unroll
        for (int p = 0; p < 2; p++) {
            const int row = wn + p * 16 + ((lane >> 4) << 3) + (lane & 7);
            b0[p] = (uint32_t)row * 128u + (uint32_t)(selb ^ ((row & 7) << 4));
        }
    }

    float d[2][4][4];
    #pragma unroll
    for (int i = 0; i < 2; i++)
        #pragma unroll
        for (int j = 0; j < 4; j++)
            #pragma unroll
            for (int k = 0; k < 4; k++) d[i][j][k] = 0.f;

    uint32_t dc[2][4][2];
    if (HAS_CORR) {
        #pragma unroll
        for (int i = 0; i < 2; i++)
            #pragma unroll
            for (int j = 0; j < 4; j++) { dc[i][j][0] = 0u; dc[i][j][1] = 0u; }
    }

    // prologue
    load_stage(0, 0);
    load_stage(1, 1);
    if (NSTAGES == 3) load_stage(2, 2);
    CP_WAIT(NSTAGES - 1);
    __syncthreads();

    uint32_t ah[2][8], bh[2][8];

    for (int t = 0; t < TSTAGES; t++) {
        const uint32_t sb = sbase + (uint32_t)(t % NSTAGES) * STAGE_B;

        // stage-entry fragment load (k16 = 0) into buffer 0
        #pragma unroll
        for (int mi = 0; mi < 2; mi++) ldsm_x4(&ah[0][mi * 4], sb + a0[mi]);
        #pragma unroll
        for (int p = 0; p < 2; p++) ldsm_x4(&bh[0][p * 4], sb + OFF_BHI + b0[p]);

        #pragma unroll
        for (int k16 = 0; k16 < 4; k16++) {
            const int c = k16 & 1, nx = c ^ 1;
            if (k16 < 3) {
                const uint32_t kb = (uint32_t)(k16 + 1) * 32;
                #pragma unroll
                for (int mi = 0; mi < 2; mi++) ldsm_x4(&ah[nx][mi * 4], sb + (a0[mi] ^ kb));
                #pragma unroll
                for (int p = 0; p < 2; p++) ldsm_x4(&bh[nx][p * 4], sb + OFF_BHI + (b0[p] ^ kb));
            }
            #pragma unroll
            for (int mi = 0; mi < 2; mi++)
                #pragma unroll
                for (int nj = 0; nj < 4; nj++)
                    mma16816(d[mi][nj], &ah[c][mi * 4], &bh[c][(nj >> 1) * 4 + (nj & 1) * 2]);
            if (HAS_CORR) {
                const uint32_t kb = (uint32_t)k16 * 32;
                #pragma unroll
                for (int mi = 0; mi < 2; mi++) ldsm_x4(&ah[c][mi * 4], sb + OFF_ALO + (a0[mi] ^ kb));
                #pragma unroll
                for (int mi = 0; mi < 2; mi++)
                    #pragma unroll
                    for (int nj = 0; nj < 4; nj++)
                        mma16816h(dc[mi][nj], &ah[c][mi * 4], &bh[c][(nj >> 1) * 4 + (nj & 1) * 2]);
            }
        }

        if (NSTAGES == 2) {
            // 2-stage: reads of slot t%2 done -> barrier -> overwrite it
            __syncthreads();
            if (t + 2 < TSTAGES) {
                load_stage(t + 2, t & 1);
                CP_WAIT(1);
            } else {
                CP_WAIT(0);
            }
            __syncthreads();
        } else {
            // 3-stage: distance-2 load into the OLDEST slot ((t+2)%3 == (t-1)%3),
            // whose readers all passed the barrier at the end of iter t-1.
            if (t + 2 < TSTAGES) {
                load_stage(t + 2, (t + 2) % 3);
                CP_WAIT(1);
            } else {
                CP_WAIT(0);
            }
            __syncthreads();
        }
    }

    // ---- epilogue -----------------------------------------------------------
    #pragma unroll
    for (int mi = 0; mi < 2; mi++) {
        const int row0 = mT * 128 + wm + mi * 16 + (lane >> 2);
        #pragma unroll
        for (int nj = 0; nj < 4; nj++) {
            const int col = nT * 64 + wn + nj * 8 + (lane & 3) * 2;
            float v0 = d[mi][nj][0], v1 = d[mi][nj][1];
            float v2 = d[mi][nj][2], v3 = d[mi][nj][3];
            if (HAS_CORR) {
                const __half2 c01 = *reinterpret_cast<const __half2*>(&dc[mi][nj][0]);
                const __half2 c23 = *reinterpret_cast<const __half2*>(&dc[mi][nj][1]);
                v0 += __half2float(c01.x); v1 += __half2float(c01.y);
                v2 += __half2float(c23.x); v3 += __half2float(c23.y);
            }
            float2 o0, o1;
            if (EPI == 1) {
                const float w0 = __ldg(&wsq[col]);
                const float w1 = __ldg(&wsq[col + 1]);
                o0.x = 2.f * v0 - w0; o0.y = 2.f * v1 - w1;
                o1.x = 2.f * v2 - w0; o1.y = 2.f * v3 - w1;
            } else {
                o0.x = v0; o0.y = v1;
                o1.x = v2; o1.y = v3;
            }
            *reinterpret_cast<float2*>(C + (size_t)row0 * 1024 + col) = o0;
            *reinterpret_cast<float2*>(C + (size_t)(row0 + 8) * 1024 + col) = o1;
        }
    }
}

// ---------------------------------------------------------------------------
extern "C" void kernel_launch(void* const* d_in, const int* in_sizes, int n_in,
                              void* d_out, int out_size) {
    const float* x = (const float*)d_in[0];   // [16384, 1024]
    const float* w = (const float*)d_in[1];   // [32, 32, 1024] = [1024, 1024]
    float* out = (float*)d_out;               // [16384, 1024]

    float *logits, *wsq;
    __half *xhi, *xlo, *whi, *wthi, *phi;
    cudaGetSymbolAddress((void**)&logits, g_logits);
    cudaGetSymbolAddress((void**)&wsq,    g_wsq);
    cudaGetSymbolAddress((void**)&xhi,    g_xhi);
    cudaGetSymbolAddress((void**)&xlo,    g_xlo);
    cudaGetSymbolAddress((void**)&whi,    g_whi);
    cudaGetSymbolAddress((void**)&wthi,   g_wthi);
    cudaGetSymbolAddress((void**)&phi,    g_phi);

    // GEMM1: 2 stages x (2*16KB + 8KB) = 81920 B;  GEMM2: 3 x 24KB = 73728 B
    const int SMEM1 = 2 * (2 * TILE_A16 + TILE_B16) + 1024;
    const int SMEM2 = 3 * (TILE_A16 + TILE_B16) + 1024;
    cudaFuncSetAttribute(mma_gemm<1, 2>, cudaFuncAttributeMaxDynamicSharedMemorySize, SMEM1);
    cudaFuncSetAttribute(mma_gemm<0, 1>, cudaFuncAttributeMaxDynamicSharedMemorySize, SMEM2);

    // prologue conversions
    wsq_kernel<<<NCODE, 256>>>(w, wsq);
    const int xn4 = BROWS * DIM / 4;
    split_kernel<<<(xn4 + 255) / 256, 256>>>(x, xhi, xlo, xn4);
    wprep_kernel<<<dim3(32, 32), dim3(32, 32)>>>(w, whi, wthi);

    // GEMM1: logits = 2*x@W^T - wsq   (2 terms: xhi*whi f32 + xlo*whi f16)
    mma_gemm<1, 2><<<dim3(NCODE / 64, BROWS / 128), 256, SMEM1>>>(
        xhi, xlo, whi, logits, wsq);

    // combine: double softmax + product + normalize -> P (fp16)
    combine_kernel<<<BROWS, 256>>>(logits, phi);

    // GEMM2: out = Phi @ fp16(W)   (1 term; B operand = W^T, K-major)
    mma_gemm<0, 1><<<dim3(DIM / 64, BROWS / 128), 256, SMEM2>>>(
        phi, nullptr, wthi, out, nullptr);
}

// round 16
// speedup vs baseline: 1.1675x; 1.1675x over previous
#include <cuda_runtime.h>
#include <cuda_fp16.h>
#include <math.h>
#include <stdint.h>

// Problem shape (fixed): B=16384 rows, D=1024, grid 32x32 -> N=1024 codes
#define BROWS 16384
#define DIM   1024
#define NCODE 1024

// ---------------- scratch (__device__ globals; allocation-free rule) -------
__device__ float g_logits[(size_t)BROWS * NCODE];    // 64MB
__device__ float g_wsq[NCODE];
__device__ __half g_xhi[(size_t)BROWS * DIM];
__device__ __half g_xlo[(size_t)BROWS * DIM];
__device__ __half g_whi[(size_t)NCODE * DIM];
__device__ __half g_wthi[(size_t)DIM * NCODE];
__device__ __half g_phi[(size_t)BROWS * NCODE];

// ---------------- PTX helpers ----------------------------------------------
__device__ __forceinline__ uint32_t s2u(const void* p) {
    uint32_t a;
    asm("{ .reg .u64 t; cvta.to.shared.u64 t, %1; cvt.u32.u64 %0, t; }" : "=r"(a) : "l"(p));
    return a;
}
__device__ __forceinline__ uint32_t swz128(uint32_t o) { return o ^ ((o >> 3) & 0x70); }

__device__ __forceinline__ void cpa16(uint32_t dst, const void* src) {
    asm volatile("cp.async.cg.shared.global [%0], [%1], 16;" :: "r"(dst), "l"(src));
}
#define CP_COMMIT() asm volatile("cp.async.commit_group;")
#define CP_WAIT(n)  asm volatile("cp.async.wait_group %0;" :: "n"(n))

__device__ __forceinline__ void ldsm_x4(uint32_t* r, uint32_t addr) {
    asm volatile("ldmatrix.sync.aligned.m8n8.x4.shared.b16 {%0,%1,%2,%3}, [%4];"
                 : "=r"(r[0]), "=r"(r[1]), "=r"(r[2]), "=r"(r[3]) : "r"(addr));
}
__device__ __forceinline__ void mma16816(float* d, const uint32_t* a, const uint32_t* b) {
    asm volatile("mma.sync.aligned.m16n8k16.row.col.f32.f16.f16.f32 "
                 "{%0,%1,%2,%3}, {%4,%5,%6,%7}, {%8,%9}, {%0,%1,%2,%3};"
                 : "+f"(d[0]), "+f"(d[1]), "+f"(d[2]), "+f"(d[3])
                 : "r"(a[0]), "r"(a[1]), "r"(a[2]), "r"(a[3]), "r"(b[0]), "r"(b[1]));
}
// f16-accumulator HMMA (for small correction term)
__device__ __forceinline__ void mma16816h(uint32_t* d, const uint32_t* a, const uint32_t* b) {
    asm volatile("mma.sync.aligned.m16n8k16.row.col.f16.f16.f16.f16 "
                 "{%0,%1}, {%2,%3,%4,%5}, {%6,%7}, {%0,%1};"
                 : "+r"(d[0]), "+r"(d[1])
                 : "r"(a[0]), "r"(a[1]), "r"(a[2]), "r"(a[3]), "r"(b[0]), "r"(b[1]));
}

// ---------------- small kernels ---------------------------------------------
__global__ void wsq_kernel(const float* __restrict__ W, float* __restrict__ wsq) {
    const int n = blockIdx.x, tid = threadIdx.x;
    const float4 v = *reinterpret_cast<const float4*>(W + (size_t)n * DIM + tid * 4);
    float s = v.x * v.x + v.y * v.y + v.z * v.z + v.w * v.w;
    __shared__ float red[256];
    red[tid] = s;
    __syncthreads();
    #pragma unroll
    for (int st = 128; st > 0; st >>= 1) {
        if (tid < st) red[tid] += red[tid + st];
        __syncthreads();
    }
    if (tid == 0) wsq[n] = red[0];
}

// hi = f16(v), lo = f16(v - hi). 4 elems/thread. (x only)
__global__ void split_kernel(const float* __restrict__ src,
                             __half* __restrict__ hi, __half* __restrict__ lo, int n4) {
    int i = blockIdx.x * blockDim.x + threadIdx.x;
    if (i >= n4) return;
    float4 v = reinterpret_cast<const float4*>(src)[i];
    __half h0 = __float2half_rn(v.x), h1 = __float2half_rn(v.y);
    __half h2 = __float2half_rn(v.z), h3 = __float2half_rn(v.w);
    __half l0 = __float2half_rn(v.x - __half2float(h0));
    __half l1 = __float2half_rn(v.y - __half2float(h1));
    __half l2 = __float2half_rn(v.z - __half2float(h2));
    __half l3 = __float2half_rn(v.w - __half2float(h3));
    __half2* ph = reinterpret_cast<__half2*>(hi) + 2 * i;
    __half2* pl = reinterpret_cast<__half2*>(lo) + 2 * i;
    ph[0] = __halves2half2(h0, h1); ph[1] = __halves2half2(h2, h3);
    pl[0] = __halves2half2(l0, l1); pl[1] = __halves2half2(l2, l3);
}

// W prep (fused): whi[n][d] = f16(W[n][d]); wthi[d][n] = f16(W[n][d]).
__global__ void wprep_kernel(const float* __restrict__ W,
                             __half* __restrict__ Whi,
                             __half* __restrict__ WThi) {
    __shared__ float tile[32][33];
    const int tx = threadIdx.x, ty = threadIdx.y;
    const int bd = blockIdx.x, bn = blockIdx.y;
    const float v = W[(size_t)(bn * 32 + ty) * DIM + bd * 32 + tx];
    tile[ty][tx] = v;
    Whi[(size_t)(bn * 32 + ty) * DIM + bd * 32 + tx] = __float2half_rn(v);
    __syncthreads();
    WThi[(size_t)(bd * 32 + ty) * NCODE + bn * 32 + tx] = __float2half_rn(tile[tx][ty]);
}

// per-row double softmax + product + normalize; emits fp16 P.
__global__ void combine_kernel(const float* __restrict__ L,
                               __half* __restrict__ Phi) {
    const int b = blockIdx.x, tid = threadIdx.x;
    const int lane = tid & 31, wp = tid >> 5;
    const float* row = L + (size_t)b * 1024;

    __shared__ float sh_e[1024 + 32];  // stride-33 padded
    __shared__ float wred[8];
    __shared__ float iRS[32], iCS[32];
    __shared__ float sh_bcast[2];

    const int n0 = tid * 4;
    float4 v = *reinterpret_cast<const float4*>(row + n0);

    float m = fmaxf(fmaxf(v.x, v.y), fmaxf(v.z, v.w));
    #pragma unroll
    for (int s = 16; s > 0; s >>= 1)
        m = fmaxf(m, __shfl_xor_sync(0xffffffffu, m, s));
    if (lane == 0) wred[wp] = m;
    __syncthreads();
    if (tid == 0) {
        float mm = wred[0];
        #pragma unroll
        for (int i = 1; i < 8; i++) mm = fmaxf(mm, wred[i]);
        sh_bcast[0] = mm;
    }
    __syncthreads();
    const float M = sh_bcast[0];

    const float e0 = __expf(v.x - M), e1 = __expf(v.y - M);
    const float e2 = __expf(v.z - M), e3 = __expf(v.w - M);
    sh_e[(n0 + 0) + ((n0 + 0) >> 5)] = e0;
    sh_e[(n0 + 1) + ((n0 + 1) >> 5)] = e1;
    sh_e[(n0 + 2) + ((n0 + 2) >> 5)] = e2;
    sh_e[(n0 + 3) + ((n0 + 3) >> 5)] = e3;
    __syncthreads();

    if (tid < 32) {
        float s = 0.f;
        #pragma unroll
        for (int j = 0; j < 32; j++) s += sh_e[tid * 33 + j];
        iRS[tid] = __fdividef(1.f, s);
    } else if (tid < 64) {
        const int g2 = tid - 32;
        float s = 0.f;
        #pragma unroll
        for (int j = 0; j < 32; j++) s += sh_e[j * 33 + g2];
        iCS[g2] = __fdividef(1.f, s);
    }
    __syncthreads();

    const int g1 = n0 >> 5, g2 = n0 & 31;
    const float irs = iRS[g1];
    const float c0 = e0 * e0 * irs * iCS[g2 + 0];
    const float c1 = e1 * e1 * irs * iCS[g2 + 1];
    const float c2 = e2 * e2 * irs * iCS[g2 + 2];
    const float c3 = e3 * e3 * irs * iCS[g2 + 3];

    float s = c0 + c1 + c2 + c3;
    #pragma unroll
    for (int st = 16; st > 0; st >>= 1)
        s += __shfl_xor_sync(0xffffffffu, s, st);
    if (lane == 0) wred[wp] = s;
    __syncthreads();
    if (tid == 0) {
        float ss = 0.f;
        #pragma unroll
        for (int i = 0; i < 8; i++) ss += wred[i];
        sh_bcast[1] = __fdividef(1.0f, ss + 1e-8f);
    }
    __syncthreads();
    const float inv = sh_bcast[1];

    __half h0 = __float2half_rn(c0 * inv), h1 = __float2half_rn(c1 * inv);
    __half h2 = __float2half_rn(c2 * inv), h3 = __float2half_rn(c3 * inv);
    __half2* ph = reinterpret_cast<__half2*>(Phi + (size_t)b * 1024 + n0);
    ph[0] = __halves2half2(h0, h1); ph[1] = __halves2half2(h2, h3);
}

// ---------------- mma.sync split-fp16 GEMM -----------------------------------
// CTA 64(m)x128(n), 256 threads = 8 warps (2m x 4n), warp tile 32x32.
// TWO CTAs per SM (independent barrier domains) + 3-stage single-barrier
// pipeline (R13 schedule: distance-2 load into the oldest slot).
// K-stage 64 (128B SW128 rows). Register fragment double-buffer across k16.
// TERMS==2: Ahi*Bhi (f32 acc) + Alo*Bhi (f16 acc).  TERMS==1: Ahi*Bhi only.
// EPI==1: C = 2*acc - wsq[col].
#define TILE_A16  8192                 //  64 rows x 128B
#define TILE_B16  16384                // 128 rows x 128B
#define TSTAGES   16                   // 1024 / 64

template<int EPI, int TERMS>
__global__ __launch_bounds__(256, 2)
void mma_gemm(const __half* __restrict__ Ahi, const __half* __restrict__ Alo,
              const __half* __restrict__ Bhi,
              float* __restrict__ C, const float* __restrict__ wsq)
{
    constexpr bool HAS_CORR = (TERMS == 2);
    constexpr uint32_t OFF_ALO = TILE_A16;
    constexpr uint32_t OFF_BHI = HAS_CORR ? 2 * TILE_A16 : TILE_A16;
    constexpr uint32_t STAGE_B = OFF_BHI + TILE_B16;   // 32KB / 24KB

    extern __shared__ char dyn[];
    const uint32_t sbase = (s2u(dyn) + 1023u) & ~1023u;

    const int tid  = threadIdx.x;
    const int w    = tid >> 5, lane = tid & 31;
    const int nT   = blockIdx.x, mT = blockIdx.y;
    const int wm   = (w >> 2) * 32;    // 2 warps along m (64 rows)
    const int wn   = (w & 3) * 32;     // 4 warps along n (128 cols)

    // ---- gmem loader geometry ------------------------------------------------
    // A: 64 rows, 4 threads/row, each 2x16B.  B: 128 rows, 2 threads/row, 4x16B.
    const int ar = tid >> 2;
    const uint32_t ac = (tid & 3) * 32;
    const int br = tid >> 1;
    const uint32_t bc = (tid & 1) * 64;
    uint32_t aso[2], bso[4];
    #pragma unroll
    for (int i = 0; i < 2; i++) aso[i] = swz128((uint32_t)ar * 128u + ac + i * 16);
    #pragma unroll
    for (int i = 0; i < 4; i++) bso[i] = swz128((uint32_t)br * 128u + bc + i * 16);

    const char* gAhi = (const char*)Ahi + (size_t)(mT * 64 + ar) * 2048 + ac;
    const char* gAlo = HAS_CORR ? (const char*)Alo + (size_t)(mT * 64 + ar) * 2048 + ac : nullptr;
    const char* gBhi = (const char*)Bhi + (size_t)(nT * 128 + br) * 2048 + bc;

    auto load_stage = [&](int t, int slot) {
        const uint32_t sb = sbase + (uint32_t)slot * STAGE_B;
        const size_t tb = (size_t)t * 128;   // 64 f16 = 128B along K
        #pragma unroll
        for (int i = 0; i < 2; i++) {
            cpa16(sb + aso[i], gAhi + tb + i * 16);
            if (HAS_CORR) cpa16(sb + OFF_ALO + aso[i], gAlo + tb + i * 16);
        }
        #pragma unroll
        for (int i = 0; i < 4; i++)
            cpa16(sb + OFF_BHI + bso[i], gBhi + tb + i * 16);
        CP_COMMIT();
    };

    // ---- ldmatrix base addresses (swizzled; k-step folds in via XOR) -------
    uint32_t a0[2];
    {
        const int rsel = (lane >> 4) * 16;
        #pragma unroll
        for (int mi = 0; mi < 2; mi++) {
            const int row = wm + mi * 16 + (lane & 15);
            a0[mi] = (uint32_t)row * 128u + (uint32_t)(rsel ^ ((row & 7) << 4));
        }
    }
    uint32_t b0[2];
    {
        const int selb = ((lane >> 3) & 1) * 16;
        #pragma unroll
        for (int p = 0; p < 2; p++) {
            const int row = wn + p * 16 + ((lane >> 4) << 3) + (lane & 7);
            b0[p] = (uint32_t)row * 128u + (uint32_t)(selb ^ ((row & 7) << 4));
        }
    }

    float d[2][4][4];
    #pragma unroll
    for (int i = 0; i < 2; i++)
        #pragma unroll
        for (int j = 0; j < 4; j++)
            #pragma unroll
            for (int k = 0; k < 4; k++) d[i][j][k] = 0.f;

    uint32_t dc[2][4][2];
    if (HAS_CORR) {
        #pragma unroll
        for (int i = 0; i < 2; i++)
            #pragma unroll
            for (int j = 0; j < 4; j++) { dc[i][j][0] = 0u; dc[i][j][1] = 0u; }
    }

    // prologue: stages 0,1 in flight; stage 0 complete before first compute
    load_stage(0, 0);
    load_stage(1, 1);
    CP_WAIT(1);
    __syncthreads();

    uint32_t ah[2][8], bh[2][8];

    for (int t = 0; t < TSTAGES; t++) {
        const uint32_t sb = sbase + (uint32_t)(t % 3) * STAGE_B;

        // stage-entry fragment load (k16 = 0) into buffer 0
        #pragma unroll
        for (int mi = 0; mi < 2; mi++) ldsm_x4(&ah[0][mi * 4], sb + a0[mi]);
        #pragma unroll
        for (int p = 0; p < 2; p++) ldsm_x4(&bh[0][p * 4], sb + OFF_BHI + b0[p]);

        #pragma unroll
        for (int k16 = 0; k16 < 4; k16++) {
            const int c = k16 & 1, nx = c ^ 1;
            if (k16 < 3) {
                const uint32_t kb = (uint32_t)(k16 + 1) * 32;
                #pragma unroll
                for (int mi = 0; mi < 2; mi++) ldsm_x4(&ah[nx][mi * 4], sb + (a0[mi] ^ kb));
                #pragma unroll
                for (int p = 0; p < 2; p++) ldsm_x4(&bh[nx][p * 4], sb + OFF_BHI + (b0[p] ^ kb));
            }
            #pragma unroll
            for (int mi = 0; mi < 2; mi++)
                #pragma unroll
                for (int nj = 0; nj < 4; nj++)
                    mma16816(d[mi][nj], &ah[c][mi * 4], &bh[c][(nj >> 1) * 4 + (nj & 1) * 2]);
            if (HAS_CORR) {
                const uint32_t kb = (uint32_t)k16 * 32;
                #pragma unroll
                for (int mi = 0; mi < 2; mi++) ldsm_x4(&ah[c][mi * 4], sb + OFF_ALO + (a0[mi] ^ kb));
                #pragma unroll
                for (int mi = 0; mi < 2; mi++)
                    #pragma unroll
                    for (int nj = 0; nj < 4; nj++)
                        mma16816h(dc[mi][nj], &ah[c][mi * 4], &bh[c][(nj >> 1) * 4 + (nj & 1) * 2]);
            }
        }

        // distance-2 load into the oldest slot ((t+2)%3 == (t-1)%3), whose
        // readers all passed the barrier at the end of iter t-1.
        if (t + 2 < TSTAGES) {
            load_stage(t + 2, (t + 2) % 3);
            CP_WAIT(1);
        } else {
            CP_WAIT(0);
        }
        __syncthreads();
    }

    // ---- epilogue -----------------------------------------------------------
    #pragma unroll
    for (int mi = 0; mi < 2; mi++) {
        const int row0 = mT * 64 + wm + mi * 16 + (lane >> 2);
        #pragma unroll
        for (int nj = 0; nj < 4; nj++) {
            const int col = nT * 128 + wn + nj * 8 + (lane & 3) * 2;
            float v0 = d[mi][nj][0], v1 = d[mi][nj][1];
            float v2 = d[mi][nj][2], v3 = d[mi][nj][3];
            if (HAS_CORR) {
                const __half2 c01 = *reinterpret_cast<const __half2*>(&dc[mi][nj][0]);
                const __half2 c23 = *reinterpret_cast<const __half2*>(&dc[mi][nj][1]);
                v0 += __half2float(c01.x); v1 += __half2float(c01.y);
                v2 += __half2float(c23.x); v3 += __half2float(c23.y);
            }
            float2 o0, o1;
            if (EPI == 1) {
                const float w0 = __ldg(&wsq[col]);
                const float w1 = __ldg(&wsq[col + 1]);
                o0.x = 2.f * v0 - w0; o0.y = 2.f * v1 - w1;
                o1.x = 2.f * v2 - w0; o1.y = 2.f * v3 - w1;
            } else {
                o0.x = v0; o0.y = v1;
                o1.x = v2; o1.y = v3;
            }
            *reinterpret_cast<float2*>(C + (size_t)row0 * 1024 + col) = o0;
            *reinterpret_cast<float2*>(C + (size_t)(row0 + 8) * 1024 + col) = o1;
        }
    }
}

// ---------------------------------------------------------------------------
extern "C" void kernel_launch(void* const* d_in, const int* in_sizes, int n_in,
                              void* d_out, int out_size) {
    const float* x = (const float*)d_in[0];   // [16384, 1024]
    const float* w = (const float*)d_in[1];   // [32, 32, 1024] = [1024, 1024]
    float* out = (float*)d_out;               // [16384, 1024]

    float *logits, *wsq;
    __half *xhi, *xlo, *whi, *wthi, *phi;
    cudaGetSymbolAddress((void**)&logits, g_logits);
    cudaGetSymbolAddress((void**)&wsq,    g_wsq);
    cudaGetSymbolAddress((void**)&xhi,    g_xhi);
    cudaGetSymbolAddress((void**)&xlo,    g_xlo);
    cudaGetSymbolAddress((void**)&whi,    g_whi);
    cudaGetSymbolAddress((void**)&wthi,   g_wthi);
    cudaGetSymbolAddress((void**)&phi,    g_phi);

    // GEMM1: 3 stages x 32KB = 98304 B/CTA;  GEMM2: 3 x 24KB = 73728 B/CTA
    const int SMEM1 = 3 * (2 * TILE_A16 + TILE_B16) + 1024;
    const int SMEM2 = 3 * (TILE_A16 + TILE_B16) + 1024;
    cudaFuncSetAttribute(mma_gemm<1, 2>, cudaFuncAttributeMaxDynamicSharedMemorySize, SMEM1);
    cudaFuncSetAttribute(mma_gemm<0, 1>, cudaFuncAttributeMaxDynamicSharedMemorySize, SMEM2);

    // prologue conversions
    wsq_kernel<<<NCODE, 256>>>(w, wsq);
    const int xn4 = BROWS * DIM / 4;
    split_kernel<<<(xn4 + 255) / 256, 256>>>(x, xhi, xlo, xn4);
    wprep_kernel<<<dim3(32, 32), dim3(32, 32)>>>(w, whi, wthi);

    // GEMM1: logits = 2*x@W^T - wsq   (2 terms: xhi*whi f32 + xlo*whi f16)
    mma_gemm<1, 2><<<dim3(NCODE / 128, BROWS / 64), 256, SMEM1>>>(
        xhi, xlo, whi, logits, wsq);

    // combine: double softmax + product + normalize -> P (fp16)
    combine_kernel<<<BROWS, 256>>>(logits, phi);

    // GEMM2: out = Phi @ fp16(W)   (1 term; B operand = W^T, K-major)
    mma_gemm<0, 1><<<dim3(DIM / 128, BROWS / 64), 256, SMEM2>>>(
        phi, nullptr, wthi, out, nullptr);
}

// round 17
// speedup vs baseline: 1.2423x; 1.0641x over previous
#include <cuda_runtime.h>
#include <cuda_fp16.h>
#include <math.h>
#include <stdint.h>

// Problem shape (fixed): B=16384 rows, D=1024, grid 32x32 -> N=1024 codes
#define BROWS 16384
#define DIM   1024
#define NCODE 1024

// ---------------- scratch (__device__ globals; allocation-free rule) -------
__device__ float g_logits[(size_t)BROWS * NCODE];    // 64MB
__device__ float g_wsq[NCODE];
__device__ __half g_xhi[(size_t)BROWS * DIM];
__device__ __half g_xlo[(size_t)BROWS * DIM];
__device__ __half g_whi[(size_t)NCODE * DIM];
__device__ __half g_wthi[(size_t)DIM * NCODE];
__device__ __half g_phi[(size_t)BROWS * NCODE];

// ---------------- PTX helpers ----------------------------------------------
__device__ __forceinline__ uint32_t s2u(const void* p) {
    uint32_t a;
    asm("{ .reg .u64 t; cvta.to.shared.u64 t, %1; cvt.u32.u64 %0, t; }" : "=r"(a) : "l"(p));
    return a;
}
__device__ __forceinline__ uint32_t swz128(uint32_t o) { return o ^ ((o >> 3) & 0x70); }

__device__ __forceinline__ void cpa16(uint32_t dst, const void* src) {
    asm volatile("cp.async.cg.shared.global [%0], [%1], 16;" :: "r"(dst), "l"(src));
}
#define CP_COMMIT() asm volatile("cp.async.commit_group;")
#define CP_WAIT(n)  asm volatile("cp.async.wait_group %0;" :: "n"(n))

__device__ __forceinline__ void ldsm_x4(uint32_t* r, uint32_t addr) {
    asm volatile("ldmatrix.sync.aligned.m8n8.x4.shared.b16 {%0,%1,%2,%3}, [%4];"
                 : "=r"(r[0]), "=r"(r[1]), "=r"(r[2]), "=r"(r[3]) : "r"(addr));
}
__device__ __forceinline__ void mma16816(float* d, const uint32_t* a, const uint32_t* b) {
    asm volatile("mma.sync.aligned.m16n8k16.row.col.f32.f16.f16.f32 "
                 "{%0,%1,%2,%3}, {%4,%5,%6,%7}, {%8,%9}, {%0,%1,%2,%3};"
                 : "+f"(d[0]), "+f"(d[1]), "+f"(d[2]), "+f"(d[3])
                 : "r"(a[0]), "r"(a[1]), "r"(a[2]), "r"(a[3]), "r"(b[0]), "r"(b[1]));
}
// f16-accumulator HMMA (for small correction term)
__device__ __forceinline__ void mma16816h(uint32_t* d, const uint32_t* a, const uint32_t* b) {
    asm volatile("mma.sync.aligned.m16n8k16.row.col.f16.f16.f16.f16 "
                 "{%0,%1}, {%2,%3,%4,%5}, {%6,%7}, {%0,%1};"
                 : "+r"(d[0]), "+r"(d[1])
                 : "r"(a[0]), "r"(a[1]), "r"(a[2]), "r"(a[3]), "r"(b[0]), "r"(b[1]));
}

// ---------------- small kernels ---------------------------------------------
__global__ void wsq_kernel(const float* __restrict__ W, float* __restrict__ wsq) {
    const int n = blockIdx.x, tid = threadIdx.x;
    const float4 v = *reinterpret_cast<const float4*>(W + (size_t)n * DIM + tid * 4);
    float s = v.x * v.x + v.y * v.y + v.z * v.z + v.w * v.w;
    __shared__ float red[256];
    red[tid] = s;
    __syncthreads();
    #pragma unroll
    for (int st = 128; st > 0; st >>= 1) {
        if (tid < st) red[tid] += red[tid + st];
        __syncthreads();
    }
    if (tid == 0) wsq[n] = red[0];
}

// hi = f16(v), lo = f16(v - hi). 4 elems/thread. (x only)
__global__ void split_kernel(const float* __restrict__ src,
                             __half* __restrict__ hi, __half* __restrict__ lo, int n4) {
    int i = blockIdx.x * blockDim.x + threadIdx.x;
    if (i >= n4) return;
    float4 v = reinterpret_cast<const float4*>(src)[i];
    __half h0 = __float2half_rn(v.x), h1 = __float2half_rn(v.y);
    __half h2 = __float2half_rn(v.z), h3 = __float2half_rn(v.w);
    __half l0 = __float2half_rn(v.x - __half2float(h0));
    __half l1 = __float2half_rn(v.y - __half2float(h1));
    __half l2 = __float2half_rn(v.z - __half2float(h2));
    __half l3 = __float2half_rn(v.w - __half2float(h3));
    __half2* ph = reinterpret_cast<__half2*>(hi) + 2 * i;
    __half2* pl = reinterpret_cast<__half2*>(lo) + 2 * i;
    ph[0] = __halves2half2(h0, h1); ph[1] = __halves2half2(h2, h3);
    pl[0] = __halves2half2(l0, l1); pl[1] = __halves2half2(l2, l3);
}

// W prep (fused): whi[n][d] = f16(W[n][d]); wthi[d][n] = f16(W[n][d]).
__global__ void wprep_kernel(const float* __restrict__ W,
                             __half* __restrict__ Whi,
                             __half* __restrict__ WThi) {
    __shared__ float tile[32][33];
    const int tx = threadIdx.x, ty = threadIdx.y;
    const int bd = blockIdx.x, bn = blockIdx.y;
    const float v = W[(size_t)(bn * 32 + ty) * DIM + bd * 32 + tx];
    tile[ty][tx] = v;
    Whi[(size_t)(bn * 32 + ty) * DIM + bd * 32 + tx] = __float2half_rn(v);
    __syncthreads();
    WThi[(size_t)(bd * 32 + ty) * NCODE + bn * 32 + tx] = __float2half_rn(tile[tx][ty]);
}

// per-row double softmax + product + normalize; emits fp16 P.
// 512 threads handle TWO rows per block (halves per-row barrier overhead).
__global__ void combine_kernel(const float* __restrict__ L,
                               __half* __restrict__ Phi) {
    const int tid = threadIdx.x;
    const int r   = tid >> 8;            // 0 or 1: which row half
    const int rt  = tid & 255;           // thread index within the row
    const int lane = tid & 31, wp = (rt >> 5);
    const int b = blockIdx.x * 2 + r;
    const float* row = L + (size_t)b * 1024;

    __shared__ float sh_e[2][1024 + 32];   // stride-33 padded per row
    __shared__ float wred[2][8];
    __shared__ float iRS[2][32], iCS[2][32];
    __shared__ float sh_bcast[2][2];

    const int n0 = rt * 4;
    float4 v = *reinterpret_cast<const float4*>(row + n0);

    float m = fmaxf(fmaxf(v.x, v.y), fmaxf(v.z, v.w));
    #pragma unroll
    for (int s = 16; s > 0; s >>= 1)
        m = fmaxf(m, __shfl_xor_sync(0xffffffffu, m, s));
    if (lane == 0) wred[r][wp] = m;
    __syncthreads();
    if (rt == 0) {
        float mm = wred[r][0];
        #pragma unroll
        for (int i = 1; i < 8; i++) mm = fmaxf(mm, wred[r][i]);
        sh_bcast[r][0] = mm;
    }
    __syncthreads();
    const float M = sh_bcast[r][0];

    const float e0 = __expf(v.x - M), e1 = __expf(v.y - M);
    const float e2 = __expf(v.z - M), e3 = __expf(v.w - M);
    sh_e[r][(n0 + 0) + ((n0 + 0) >> 5)] = e0;
    sh_e[r][(n0 + 1) + ((n0 + 1) >> 5)] = e1;
    sh_e[r][(n0 + 2) + ((n0 + 2) >> 5)] = e2;
    sh_e[r][(n0 + 3) + ((n0 + 3) >> 5)] = e3;
    __syncthreads();

    if (rt < 32) {
        float s = 0.f;
        #pragma unroll
        for (int j = 0; j < 32; j++) s += sh_e[r][rt * 33 + j];
        iRS[r][rt] = __fdividef(1.f, s);
    } else if (rt < 64) {
        const int g2 = rt - 32;
        float s = 0.f;
        #pragma unroll
        for (int j = 0; j < 32; j++) s += sh_e[r][j * 33 + g2];
        iCS[r][g2] = __fdividef(1.f, s);
    }
    __syncthreads();

    const int g1 = n0 >> 5, g2 = n0 & 31;
    const float irs = iRS[r][g1];
    const float c0 = e0 * e0 * irs * iCS[r][g2 + 0];
    const float c1 = e1 * e1 * irs * iCS[r][g2 + 1];
    const float c2 = e2 * e2 * irs * iCS[r][g2 + 2];
    const float c3 = e3 * e3 * irs * iCS[r][g2 + 3];

    float s = c0 + c1 + c2 + c3;
    #pragma unroll
    for (int st = 16; st > 0; st >>= 1)
        s += __shfl_xor_sync(0xffffffffu, s, st);
    if (lane == 0) wred[r][wp] = s;
    __syncthreads();
    if (rt == 0) {
        float ss = 0.f;
        #pragma unroll
        for (int i = 0; i < 8; i++) ss += wred[r][i];
        sh_bcast[r][1] = __fdividef(1.0f, ss + 1e-8f);
    }
    __syncthreads();
    const float inv = sh_bcast[r][1];

    __half h0 = __float2half_rn(c0 * inv), h1 = __float2half_rn(c1 * inv);
    __half h2 = __float2half_rn(c2 * inv), h3 = __float2half_rn(c3 * inv);
    __half2* ph = reinterpret_cast<__half2*>(Phi + (size_t)b * 1024 + n0);
    ph[0] = __halves2half2(h0, h1); ph[1] = __halves2half2(h2, h3);
}

// ---------------- GEMM1: split-fp16, 2 terms (R16 config, measured 181us) ----
// CTA 64(m)x128(n), 256 threads = 8 warps (2m x 4n), warp tile 32x32.
// TWO CTAs per SM; 3-stage single-barrier pipeline (distance-2 into oldest
// slot); register fragment double-buffer across k16.
// logits = 2*(xhi+xlo)@whi^T - wsq  (main f32 acc, correction f16 acc)
#define TILE_A1  8192                  //  64 rows x 128B
#define TILE_B1  16384                 // 128 rows x 128B
#define STAGE1   (2 * TILE_A1 + TILE_B1)
#define TSTAGES  16                    // 1024 / 64

__global__ __launch_bounds__(256, 2)
void mma_gemm1(const __half* __restrict__ Ahi, const __half* __restrict__ Alo,
               const __half* __restrict__ Bhi,
               float* __restrict__ C, const float* __restrict__ wsq)
{
    constexpr uint32_t OFF_ALO = TILE_A1;
    constexpr uint32_t OFF_BHI = 2 * TILE_A1;

    extern __shared__ char dyn[];
    const uint32_t sbase = (s2u(dyn) + 1023u) & ~1023u;

    const int tid  = threadIdx.x;
    const int w    = tid >> 5, lane = tid & 31;
    const int nT   = blockIdx.x, mT = blockIdx.y;
    const int wm   = (w >> 2) * 32;    // 2 warps along m (64 rows)
    const int wn   = (w & 3) * 32;     // 4 warps along n (128 cols)

    const int ar = tid >> 2;
    const uint32_t ac = (tid & 3) * 32;
    const int br = tid >> 1;
    const uint32_t bc = (tid & 1) * 64;
    uint32_t aso[2], bso[4];
    #pragma unroll
    for (int i = 0; i < 2; i++) aso[i] = swz128((uint32_t)ar * 128u + ac + i * 16);
    #pragma unroll
    for (int i = 0; i < 4; i++) bso[i] = swz128((uint32_t)br * 128u + bc + i * 16);

    const char* gAhi = (const char*)Ahi + (size_t)(mT * 64 + ar) * 2048 + ac;
    const char* gAlo = (const char*)Alo + (size_t)(mT * 64 + ar) * 2048 + ac;
    const char* gBhi = (const char*)Bhi + (size_t)(nT * 128 + br) * 2048 + bc;

    auto load_stage = [&](int t, int slot) {
        const uint32_t sb = sbase + (uint32_t)slot * STAGE1;
        const size_t tb = (size_t)t * 128;
        #pragma unroll
        for (int i = 0; i < 2; i++) {
            cpa16(sb + aso[i], gAhi + tb + i * 16);
            cpa16(sb + OFF_ALO + aso[i], gAlo + tb + i * 16);
        }
        #pragma unroll
        for (int i = 0; i < 4; i++)
            cpa16(sb + OFF_BHI + bso[i], gBhi + tb + i * 16);
        CP_COMMIT();
    };

    uint32_t a0[2];
    {
        const int rsel = (lane >> 4) * 16;
        #pragma unroll
        for (int mi = 0; mi < 2; mi++) {
            const int row = wm + mi * 16 + (lane & 15);
            a0[mi] = (uint32_t)row * 128u + (uint32_t)(rsel ^ ((row & 7) << 4));
        }
    }
    uint32_t b0[2];
    {
        const int selb = ((lane >> 3) & 1) * 16;
        #pragma unroll
        for (int p = 0; p < 2; p++) {
            const int row = wn + p * 16 + ((lane >> 4) << 3) + (lane & 7);
            b0[p] = (uint32_t)row * 128u + (uint32_t)(selb ^ ((row & 7) << 4));
        }
    }

    float d[2][4][4];
    #pragma unroll
    for (int i = 0; i < 2; i++)
        #pragma unroll
        for (int j = 0; j < 4; j++)
            #pragma unroll
            for (int k = 0; k < 4; k++) d[i][j][k] = 0.f;
    uint32_t dc[2][4][2];
    #pragma unroll
    for (int i = 0; i < 2; i++)
        #pragma unroll
        for (int j = 0; j < 4; j++) { dc[i][j][0] = 0u; dc[i][j][1] = 0u; }

    load_stage(0, 0);
    load_stage(1, 1);
    CP_WAIT(1);
    __syncthreads();

    uint32_t ah[2][8], bh[2][8];

    for (int t = 0; t < TSTAGES; t++) {
        const uint32_t sb = sbase + (uint32_t)(t % 3) * STAGE1;

        #pragma unroll
        for (int mi = 0; mi < 2; mi++) ldsm_x4(&ah[0][mi * 4], sb + a0[mi]);
        #pragma unroll
        for (int p = 0; p < 2; p++) ldsm_x4(&bh[0][p * 4], sb + OFF_BHI + b0[p]);

        #pragma unroll
        for (int k16 = 0; k16 < 4; k16++) {
            const int c = k16 & 1, nx = c ^ 1;
            if (k16 < 3) {
                const uint32_t kb = (uint32_t)(k16 + 1) * 32;
                #pragma unroll
                for (int mi = 0; mi < 2; mi++) ldsm_x4(&ah[nx][mi * 4], sb + (a0[mi] ^ kb));
                #pragma unroll
                for (int p = 0; p < 2; p++) ldsm_x4(&bh[nx][p * 4], sb + OFF_BHI + (b0[p] ^ kb));
            }
            #pragma unroll
            for (int mi = 0; mi < 2; mi++)
                #pragma unroll
                for (int nj = 0; nj < 4; nj++)
                    mma16816(d[mi][nj], &ah[c][mi * 4], &bh[c][(nj >> 1) * 4 + (nj & 1) * 2]);
            {
                const uint32_t kb = (uint32_t)k16 * 32;
                #pragma unroll
                for (int mi = 0; mi < 2; mi++) ldsm_x4(&ah[c][mi * 4], sb + OFF_ALO + (a0[mi] ^ kb));
                #pragma unroll
                for (int mi = 0; mi < 2; mi++)
                    #pragma unroll
                    for (int nj = 0; nj < 4; nj++)
                        mma16816h(dc[mi][nj], &ah[c][mi * 4], &bh[c][(nj >> 1) * 4 + (nj & 1) * 2]);
            }
        }

        if (t + 2 < TSTAGES) {
            load_stage(t + 2, (t + 2) % 3);
            CP_WAIT(1);
        } else {
            CP_WAIT(0);
        }
        __syncthreads();
    }

    #pragma unroll
    for (int mi = 0; mi < 2; mi++) {
        const int row0 = mT * 64 + wm + mi * 16 + (lane >> 2);
        #pragma unroll
        for (int nj = 0; nj < 4; nj++) {
            const int col = nT * 128 + wn + nj * 8 + (lane & 3) * 2;
            const __half2 c01 = *reinterpret_cast<const __half2*>(&dc[mi][nj][0]);
            const __half2 c23 = *reinterpret_cast<const __half2*>(&dc[mi][nj][1]);
            const float w0 = __ldg(&wsq[col]);
            const float w1 = __ldg(&wsq[col + 1]);
            float2 o0, o1;
            o0.x = 2.f * (d[mi][nj][0] + __half2float(c01.x)) - w0;
            o0.y = 2.f * (d[mi][nj][1] + __half2float(c01.y)) - w1;
            o1.x = 2.f * (d[mi][nj][2] + __half2float(c23.x)) - w0;
            o1.y = 2.f * (d[mi][nj][3] + __half2float(c23.y)) - w1;
            *reinterpret_cast<float2*>(C + (size_t)row0 * 1024 + col) = o0;
            *reinterpret_cast<float2*>(C + (size_t)(row0 + 8) * 1024 + col) = o1;
        }
    }
}

// ---------------- GEMM2: fp16 1-term (R13 config) -----------------------------
// CTA 128x128, 512 threads = 16 warps (4m x 4n), warp tile 32x32.
// 3-stage single-barrier pipeline, register fragment double-buffer.
#define TILE2    16384                 // 128 rows x 128B
#define STAGE2   (2 * TILE2)

__global__ __launch_bounds__(512, 1)
void mma_gemm2(const __half* __restrict__ A, const __half* __restrict__ B,
               float* __restrict__ C)
{
    constexpr uint32_t OFF_B = TILE2;

    extern __shared__ char dyn[];
    const uint32_t sbase = (s2u(dyn) + 1023u) & ~1023u;

    const int tid  = threadIdx.x;
    const int w    = tid >> 5, lane = tid & 31;
    const int nT   = blockIdx.x, mT = blockIdx.y;
    const int wm   = (w >> 2) * 32;
    const int wn   = (w & 3) * 32;

    const int lr = tid >> 2;
    const uint32_t lc = (tid & 3) * 32;
    const uint32_t lso0 = swz128((uint32_t)lr * 128u + lc);
    const uint32_t lso1 = swz128((uint32_t)lr * 128u + lc + 16);

    const char* gA = (const char*)A + (size_t)(mT * 128 + lr) * 2048 + lc;
    const char* gB = (const char*)B + (size_t)(nT * 128 + lr) * 2048 + lc;

    auto load_stage = [&](int t, int slot) {
        const uint32_t sb = sbase + (uint32_t)slot * STAGE2;
        const size_t tb = (size_t)t * 128;
        cpa16(sb + lso0, gA + tb);
        cpa16(sb + lso1, gA + tb + 16);
        cpa16(sb + OFF_B + lso0, gB + tb);
        cpa16(sb + OFF_B + lso1, gB + tb + 16);
        CP_COMMIT();
    };

    uint32_t a0[2];
    {
        const int rsel = (lane >> 4) * 16;
        #pragma unroll
        for (int mi = 0; mi < 2; mi++) {
            const int row = wm + mi * 16 + (lane & 15);
            a0[mi] = (uint32_t)row * 128u + (uint32_t)(rsel ^ ((row & 7) << 4));
        }
    }
    uint32_t b0[2];
    {
        const int selb = ((lane >> 3) & 1) * 16;
        #pragma unroll
        for (int p = 0; p < 2; p++) {
            const int row = wn + p * 16 + ((lane >> 4) << 3) + (lane & 7);
            b0[p] = (uint32_t)row * 128u + (uint32_t)(selb ^ ((row & 7) << 4));
        }
    }

    float d[2][4][4];
    #pragma unroll
    for (int i = 0; i < 2; i++)
        #pragma unroll
        for (int j = 0; j < 4; j++)
            #pragma unroll
            for (int k = 0; k < 4; k++) d[i][j][k] = 0.f;

    load_stage(0, 0);
    load_stage(1, 1);
    CP_WAIT(1);
    __syncthreads();

    uint32_t ah[2][8], bh[2][8];

    for (int t = 0; t < TSTAGES; t++) {
        const uint32_t sb = sbase + (uint32_t)(t % 3) * STAGE2;

        #pragma unroll
        for (int mi = 0; mi < 2; mi++) ldsm_x4(&ah[0][mi * 4], sb + a0[mi]);
        #pragma unroll
        for (int p = 0; p < 2; p++) ldsm_x4(&bh[0][p * 4], sb + OFF_B + b0[p]);

        #pragma unroll
        for (int k16 = 0; k16 < 4; k16++) {
            const int c = k16 & 1, nx = c ^ 1;
            if (k16 < 3) {
                const uint32_t kb = (uint32_t)(k16 + 1) * 32;
                #pragma unroll
                for (int mi = 0; mi < 2; mi++) ldsm_x4(&ah[nx][mi * 4], sb + (a0[mi] ^ kb));
                #pragma unroll
                for (int p = 0; p < 2; p++) ldsm_x4(&bh[nx][p * 4], sb + OFF_B + (b0[p] ^ kb));
            }
            #pragma unroll
            for (int mi = 0; mi < 2; mi++)
                #pragma unroll
                for (int nj = 0; nj < 4; nj++)
                    mma16816(d[mi][nj], &ah[c][mi * 4], &bh[c][(nj >> 1) * 4 + (nj & 1) * 2]);
        }

        if (t + 2 < TSTAGES) {
            load_stage(t + 2, (t + 2) % 3);
            CP_WAIT(1);
        } else {
            CP_WAIT(0);
        }
        __syncthreads();
    }

    #pragma unroll
    for (int mi = 0; mi < 2; mi++) {
        const int row0 = mT * 128 + wm + mi * 16 + (lane >> 2);
        #pragma unroll
        for (int nj = 0; nj < 4; nj++) {
            const int col = nT * 128 + wn + nj * 8 + (lane & 3) * 2;
            float2 o0, o1;
            o0.x = d[mi][nj][0]; o0.y = d[mi][nj][1];
            o1.x = d[mi][nj][2]; o1.y = d[mi][nj][3];
            *reinterpret_cast<float2*>(C + (size_t)row0 * 1024 + col) = o0;
            *reinterpret_cast<float2*>(C + (size_t)(row0 + 8) * 1024 + col) = o1;
        }
    }
}

// ---------------------------------------------------------------------------
extern "C" void kernel_launch(void* const* d_in, const int* in_sizes, int n_in,
                              void* d_out, int out_size) {
    const float* x = (const float*)d_in[0];   // [16384, 1024]
    const float* w = (const float*)d_in[1];   // [32, 32, 1024] = [1024, 1024]
    float* out = (float*)d_out;               // [16384, 1024]

    float *logits, *wsq;
    __half *xhi, *xlo, *whi, *wthi, *phi;
    cudaGetSymbolAddress((void**)&logits, g_logits);
    cudaGetSymbolAddress((void**)&wsq,    g_wsq);
    cudaGetSymbolAddress((void**)&xhi,    g_xhi);
    cudaGetSymbolAddress((void**)&xlo,    g_xlo);
    cudaGetSymbolAddress((void**)&whi,    g_whi);
    cudaGetSymbolAddress((void**)&wthi,   g_wthi);
    cudaGetSymbolAddress((void**)&phi,    g_phi);

    const int SMEM1 = 3 * STAGE1 + 1024;   // 3 x 32KB  = 99328 B/CTA (x2 CTAs)
    const int SMEM2 = 3 * STAGE2 + 1024;   // 3 x 32KB  = 99328 B
    cudaFuncSetAttribute(mma_gemm1, cudaFuncAttributeMaxDynamicSharedMemorySize, SMEM1);
    cudaFuncSetAttribute(mma_gemm2, cudaFuncAttributeMaxDynamicSharedMemorySize, SMEM2);

    // prologue conversions
    wsq_kernel<<<NCODE, 256>>>(w, wsq);
    const int xn4 = BROWS * DIM / 4;
    split_kernel<<<(xn4 + 255) / 256, 256>>>(x, xhi, xlo, xn4);
    wprep_kernel<<<dim3(32, 32), dim3(32, 32)>>>(w, whi, wthi);

    // GEMM1: logits = 2*x@W^T - wsq   (2 terms; 64x128 tile, 2 CTAs/SM)
    mma_gemm1<<<dim3(NCODE / 128, BROWS / 64), 256, SMEM1>>>(
        xhi, xlo, whi, logits, wsq);

    // combine: double softmax + product + normalize -> P (fp16); 2 rows/block
    combine_kernel<<<BROWS / 2, 512>>>(logits, phi);

    // GEMM2: out = Phi @ fp16(W)   (1 term; 128x128 tile, 512 threads)
    mma_gemm2<<<dim3(DIM / 128, BROWS / 128), 512, SMEM2>>>(phi, wthi, out);
}